// round 14
// baseline (speedup 1.0000x reference)
#include <cuda_runtime.h>
#include <cuda_bf16.h>
#include <cstdint>

// Problem dims
#define BB 8
#define SS 1024          // IMG*IMG
#define EE 768           // D_EMBED == D_MODEL
#define NH 12
#define DD 64

// ---------------- scratch (device globals; no allocs allowed) ----------------
__device__ float g_q[BB * SS * EE];
__device__ float g_k[BB * SS * EE];
__device__ float g_v[BB * SS * EE];
__device__ float g_ctx[BB * SS * EE];
// bf16 hi/lo planes of exp(scores): word j of row = pair (2j, 2j+1)
__device__ uint32_t g_ph[(size_t)BB * NH * SS * 512];
__device__ uint32_t g_pl[(size_t)BB * NH * SS * 512];
// per-row partial sums of exp(scores): [bh*SS + row][32 slots]
__device__ float g_partials[(size_t)BB * NH * SS * 32];

// =============================================================================
// bf16 split helpers: x = hi + lo, both bf16. Packed pairs along k.
// =============================================================================
__device__ __forceinline__ void split2_bf16(float x0, float x1,
                                            uint32_t& hw, uint32_t& lw) {
    __nv_bfloat162 h = __floats2bfloat162_rn(x0, x1);
    float2 hf = __bfloat1622float2(h);
    __nv_bfloat162 l = __floats2bfloat162_rn(x0 - hf.x, x1 - hf.y);
    hw = *reinterpret_cast<uint32_t*>(&h);
    lw = *reinterpret_cast<uint32_t*>(&l);
}

__device__ __forceinline__ void mma_bf16(float* d, const uint32_t* a, const uint32_t* b) {
    asm volatile(
        "mma.sync.aligned.m16n8k16.row.col.f32.bf16.bf16.f32 "
        "{%0,%1,%2,%3}, {%4,%5,%6,%7}, {%8,%9}, {%0,%1,%2,%3};"
        : "+f"(d[0]), "+f"(d[1]), "+f"(d[2]), "+f"(d[3])
        : "r"(a[0]), "r"(a[1]), "r"(a[2]), "r"(a[3]),
          "r"(b[0]), "r"(b[1]));
}

// Three interleaved passes over all 8 (mt,nt) accumulators (R13).
#define MMA_PASSES(acc, ah, al, bhv, blv)                                   \
    do {                                                                    \
        _Pragma("unroll")                                                   \
        for (int nt_ = 0; nt_ < 4; nt_++) {                                 \
            _Pragma("unroll")                                               \
            for (int mt_ = 0; mt_ < 2; mt_++)                               \
                mma_bf16(acc[mt_][nt_], ah[mt_], bhv[nt_]);                 \
        }                                                                   \
        _Pragma("unroll")                                                   \
        for (int nt_ = 0; nt_ < 4; nt_++) {                                 \
            _Pragma("unroll")                                               \
            for (int mt_ = 0; mt_ < 2; mt_++)                               \
                mma_bf16(acc[mt_][nt_], ah[mt_], blv[nt_]);                 \
        }                                                                   \
        _Pragma("unroll")                                                   \
        for (int nt_ = 0; nt_ < 4; nt_++) {                                 \
            _Pragma("unroll")                                               \
            for (int mt_ = 0; mt_ < 2; mt_++)                               \
                mma_bf16(acc[mt_][nt_], al[mt_], bhv[nt_]);                 \
        }                                                                   \
    } while (0)

// =============================================================================
// Kernel 1: QKV projection (R13, unchanged).
// =============================================================================
#define GP_AP 136
#define GP_BP 20
#define GP_AHo 0
#define GP_ALo 2176
#define GP_BHo 4352
#define GP_BLo 5632
#define GP_SMEM_WORDS 6912
#define GP_SMEM_BYTES (GP_SMEM_WORDS * 4)

__global__ __launch_bounds__(256) void proj_mma_kernel(
    const float* __restrict__ xq, const float* __restrict__ xk, const float* __restrict__ xv,
    const float* __restrict__ wq, const float* __restrict__ wk, const float* __restrict__ wv,
    const float* __restrict__ bq, const float* __restrict__ bk, const float* __restrict__ bv)
{
    extern __shared__ uint32_t su[];
    uint32_t* AH = su + GP_AHo;
    uint32_t* AL = su + GP_ALo;
    uint32_t* BH = su + GP_BHo;
    uint32_t* BL = su + GP_BLo;

    const int mat = blockIdx.z >> 3;
    const int b   = blockIdx.z & 7;

    const float* x; const float* w; const float* bi; float* y;
    if (mat == 0)      { x = xq; w = wq; bi = bq; y = g_q; }
    else if (mat == 1) { x = xk; w = wk; bi = bk; y = g_k; }
    else               { x = xv; w = wv; bi = bv; y = g_v; }
    x += (size_t)b * EE * SS;
    y += (size_t)b * SS * EE;

    const int m0 = blockIdx.x * 128;
    const int n0 = blockIdx.y * 64;

    const int tid  = threadIdx.x;
    const int lane = tid & 31;
    const int w8   = tid >> 5;
    const int wm   = w8 >> 1;
    const int wn   = w8 & 1;
    const int gid  = lane >> 2;
    const int ctid = lane & 3;

    float acc[2][4][4];
    #pragma unroll
    for (int i = 0; i < 2; i++)
        #pragma unroll
        for (int j = 0; j < 4; j++)
            #pragma unroll
            for (int q = 0; q < 4; q++) acc[i][j][q] = 0.f;

    for (int kg = 0; kg < EE; kg += 32) {
        __syncthreads();
        #pragma unroll
        for (int p = 0; p < 2; p++) {
            int idx = tid + p * 256;
            int j   = idx >> 5;
            int m4  = (idx & 31) << 2;
            const float* xr = x + (size_t)(kg + 2 * j) * SS + m0 + m4;
            float4 ra = *(const float4*)xr;
            float4 rb = *(const float4*)(xr + SS);
            uint4 hv, lv;
            split2_bf16(ra.x, rb.x, hv.x, lv.x);
            split2_bf16(ra.y, rb.y, hv.y, lv.y);
            split2_bf16(ra.z, rb.z, hv.z, lv.z);
            split2_bf16(ra.w, rb.w, hv.w, lv.w);
            *(uint4*)(AH + j * GP_AP + m4) = hv;
            *(uint4*)(AL + j * GP_AP + m4) = lv;
        }
        {
            int r  = tid >> 2;
            int kq = (tid & 3) << 3;
            const float* wr = w + (size_t)(n0 + r) * EE + kg + kq;
            float4 b0 = *(const float4*)wr;
            float4 b1 = *(const float4*)(wr + 4);
            uint4 hv, lv;
            split2_bf16(b0.x, b0.y, hv.x, lv.x);
            split2_bf16(b0.z, b0.w, hv.y, lv.y);
            split2_bf16(b1.x, b1.y, hv.z, lv.z);
            split2_bf16(b1.z, b1.w, hv.w, lv.w);
            *(uint4*)(BH + r * GP_BP + (tid & 3) * 4) = hv;
            *(uint4*)(BL + r * GP_BP + (tid & 3) * 4) = lv;
        }
        __syncthreads();

        #pragma unroll
        for (int kwb = 0; kwb < 16; kwb += 8) {
            uint32_t ah[2][4], al[2][4];
            #pragma unroll
            for (int mt = 0; mt < 2; mt++) {
                int mrow = wm * 32 + mt * 16 + gid;
                const uint32_t* ph = AH + (kwb + ctid) * GP_AP + mrow;
                const uint32_t* pl = AL + (kwb + ctid) * GP_AP + mrow;
                ah[mt][0] = ph[0];          ah[mt][1] = ph[8];
                ah[mt][2] = ph[4*GP_AP];    ah[mt][3] = ph[4*GP_AP + 8];
                al[mt][0] = pl[0];          al[mt][1] = pl[8];
                al[mt][2] = pl[4*GP_AP];    al[mt][3] = pl[4*GP_AP + 8];
            }
            uint32_t bhv[4][2], blv[4][2];
            #pragma unroll
            for (int nt = 0; nt < 4; nt++) {
                int nrow = wn * 32 + nt * 8 + gid;
                const uint32_t* pbh = BH + nrow * GP_BP + kwb + ctid;
                const uint32_t* pbl = BL + nrow * GP_BP + kwb + ctid;
                bhv[nt][0] = pbh[0]; bhv[nt][1] = pbh[4];
                blv[nt][0] = pbl[0]; blv[nt][1] = pbl[4];
            }
            MMA_PASSES(acc, ah, al, bhv, blv);
        }
    }

    #pragma unroll
    for (int nt = 0; nt < 4; nt++) {
        int col = n0 + wn * 32 + nt * 8 + 2 * ctid;
        float b0 = bi[col], b1 = bi[col + 1];
        #pragma unroll
        for (int mt = 0; mt < 2; mt++) {
            int row = m0 + wm * 32 + mt * 16 + gid;
            *(float2*)(y + (size_t)row * EE + col) =
                make_float2(acc[mt][nt][0] + b0, acc[mt][nt][1] + b1);
            *(float2*)(y + (size_t)(row + 8) * EE + col) =
                make_float2(acc[mt][nt][2] + b0, acc[mt][nt][3] + b1);
        }
    }
}

// =============================================================================
// Kernel 2a: scores GEMM + fused exp -> bf16 hi/lo plane output + partials.
// (No max subtraction: scores ~N(0,1), |s| <~ 6, exp safe in fp32.)
// =============================================================================
#define SK_P 36
#define SK_AHo 0
#define SK_ALo 4608
#define SK_BHo 9216
#define SK_BLo 11520
#define SK_SMEM_WORDS 13824
#define SK_SMEM_BYTES (SK_SMEM_WORDS * 4)

__global__ __launch_bounds__(256) void scores_mma_kernel()
{
    extern __shared__ uint32_t su[];
    uint32_t* AH = su + SK_AHo;
    uint32_t* AL = su + SK_ALo;
    uint32_t* BH = su + SK_BHo;
    uint32_t* BL = su + SK_BLo;

    const int bh = blockIdx.z;
    const int b  = bh / NH;
    const int h  = bh % NH;
    const int m0 = blockIdx.x * 128;
    const int n0 = blockIdx.y * 64;

    const float* qp = g_q + ((size_t)b * SS) * EE + h * DD;
    const float* kp = g_k + ((size_t)b * SS) * EE + h * DD;

    const int tid  = threadIdx.x;
    const int lane = tid & 31;
    const int w8   = tid >> 5;
    const int wm   = w8 >> 1;
    const int wn   = w8 & 1;
    const int gid  = lane >> 2;
    const int ctid = lane & 3;

    #pragma unroll
    for (int p = 0; p < 4; p++) {
        int idx = tid + p * 256;
        int r   = idx >> 3;
        int kq  = (idx & 7) << 3;
        const float* qr = qp + (size_t)(m0 + r) * EE + kq;
        float4 a0 = *(const float4*)qr;
        float4 a1 = *(const float4*)(qr + 4);
        uint4 hv, lv;
        split2_bf16(a0.x, a0.y, hv.x, lv.x);
        split2_bf16(a0.z, a0.w, hv.y, lv.y);
        split2_bf16(a1.x, a1.y, hv.z, lv.z);
        split2_bf16(a1.z, a1.w, hv.w, lv.w);
        *(uint4*)(AH + r * SK_P + (idx & 7) * 4) = hv;
        *(uint4*)(AL + r * SK_P + (idx & 7) * 4) = lv;
    }
    #pragma unroll
    for (int p = 0; p < 2; p++) {
        int idx = tid + p * 256;
        int r   = idx >> 3;
        int kq  = (idx & 7) << 3;
        const float* kr = kp + (size_t)(n0 + r) * EE + kq;
        float4 b0 = *(const float4*)kr;
        float4 b1 = *(const float4*)(kr + 4);
        uint4 hv, lv;
        split2_bf16(b0.x, b0.y, hv.x, lv.x);
        split2_bf16(b0.z, b0.w, hv.y, lv.y);
        split2_bf16(b1.x, b1.y, hv.z, lv.z);
        split2_bf16(b1.z, b1.w, hv.w, lv.w);
        *(uint4*)(BH + r * SK_P + (idx & 7) * 4) = hv;
        *(uint4*)(BL + r * SK_P + (idx & 7) * 4) = lv;
    }
    __syncthreads();

    float acc[2][4][4];
    #pragma unroll
    for (int i = 0; i < 2; i++)
        #pragma unroll
        for (int j = 0; j < 4; j++)
            #pragma unroll
            for (int q = 0; q < 4; q++) acc[i][j][q] = 0.f;

    #pragma unroll
    for (int kwb = 0; kwb < 32; kwb += 8) {
        uint32_t ah[2][4], al[2][4];
        #pragma unroll
        for (int mt = 0; mt < 2; mt++) {
            int mrow = wm * 32 + mt * 16 + gid;
            const uint32_t* ph = AH + mrow * SK_P + kwb + ctid;
            const uint32_t* pl = AL + mrow * SK_P + kwb + ctid;
            ah[mt][0] = ph[0];          ah[mt][1] = ph[8*SK_P];
            ah[mt][2] = ph[4];          ah[mt][3] = ph[8*SK_P + 4];
            al[mt][0] = pl[0];          al[mt][1] = pl[8*SK_P];
            al[mt][2] = pl[4];          al[mt][3] = pl[8*SK_P + 4];
        }
        uint32_t bhv[4][2], blv[4][2];
        #pragma unroll
        for (int nt = 0; nt < 4; nt++) {
            int nrow = wn * 32 + nt * 8 + gid;
            const uint32_t* pbh = BH + nrow * SK_P + kwb + ctid;
            const uint32_t* pbl = BL + nrow * SK_P + kwb + ctid;
            bhv[nt][0] = pbh[0]; bhv[nt][1] = pbh[4];
            blv[nt][0] = pbl[0]; blv[nt][1] = pbl[4];
        }
        MMA_PASSES(acc, ah, al, bhv, blv);
    }

    // ---- fused exp epilogue: bf16 hi/lo planes + per-row partial sums ----
    uint32_t* php = g_ph + (size_t)bh * SS * 512;
    uint32_t* plp = g_pl + (size_t)bh * SS * 512;
    float rs[2][2];
    rs[0][0] = rs[0][1] = rs[1][0] = rs[1][1] = 0.f;

    #pragma unroll
    for (int mt = 0; mt < 2; mt++)
        #pragma unroll
        for (int nt = 0; nt < 4; nt++) {
            float e0 = __expf(acc[mt][nt][0] * 0.125f);
            float e1 = __expf(acc[mt][nt][1] * 0.125f);
            float e2 = __expf(acc[mt][nt][2] * 0.125f);
            float e3 = __expf(acc[mt][nt][3] * 0.125f);
            int row = m0 + wm * 32 + mt * 16 + gid;
            int wrd = (n0 + wn * 32 + nt * 8 + 2 * ctid) >> 1;
            uint32_t hw, lw;
            split2_bf16(e0, e1, hw, lw);
            php[(size_t)row * 512 + wrd] = hw;
            plp[(size_t)row * 512 + wrd] = lw;
            split2_bf16(e2, e3, hw, lw);
            php[(size_t)(row + 8) * 512 + wrd] = hw;
            plp[(size_t)(row + 8) * 512 + wrd] = lw;
            rs[mt][0] += e0 + e1;
            rs[mt][1] += e2 + e3;
        }

    #pragma unroll
    for (int o = 1; o <= 2; o <<= 1) {
        rs[0][0] += __shfl_xor_sync(0xFFFFFFFFu, rs[0][0], o);
        rs[0][1] += __shfl_xor_sync(0xFFFFFFFFu, rs[0][1], o);
        rs[1][0] += __shfl_xor_sync(0xFFFFFFFFu, rs[1][0], o);
        rs[1][1] += __shfl_xor_sync(0xFFFFFFFFu, rs[1][1], o);
    }
    if (ctid == 0) {
        int slot = blockIdx.y * 2 + wn;   // 0..31
        #pragma unroll
        for (int mt = 0; mt < 2; mt++) {
            int row = m0 + wm * 32 + mt * 16 + gid;
            g_partials[((size_t)bh * SS + row) * 32 + slot]     = rs[mt][0];
            g_partials[((size_t)bh * SS + row + 8) * 32 + slot] = rs[mt][1];
        }
    }
}

// =============================================================================
// Kernel 2c: ctx GEMM reading exp planes (copy-only A staging), writing
// normalized fp32 probs (fire-and-forget) and inv-scaled ctx output.
// =============================================================================
#define CX_AP 20
#define CX_BP 72
#define CX_AHo 0
#define CX_ALo 2560
#define CX_BHo 5120
#define CX_BLo 6272
#define CX_SMEM_WORDS 7424
#define CX_SMEM_BYTES (CX_SMEM_WORDS * 4)

__global__ __launch_bounds__(256, 3) void ctx_mma_kernel(float* __restrict__ probs)
{
    extern __shared__ uint32_t su[];
    uint32_t* AH = su + CX_AHo;
    uint32_t* AL = su + CX_ALo;
    uint32_t* BH = su + CX_BHo;
    uint32_t* BL = su + CX_BLo;

    __shared__ float invs[128];

    const int bh = blockIdx.z;
    const int b  = bh / NH;
    const int h  = bh % NH;
    const int m0 = blockIdx.x * 128;

    const uint32_t* php = g_ph + (size_t)bh * SS * 512;
    const uint32_t* plp = g_pl + (size_t)bh * SS * 512;
    float* pout = probs + (size_t)bh * SS * SS;
    const float* vb = g_v + ((size_t)b * SS) * EE + h * DD;

    const int tid  = threadIdx.x;
    const int lane = tid & 31;
    const int w8   = tid >> 5;
    const int wm   = w8 >> 1;
    const int wn   = w8 & 1;
    const int gid  = lane >> 2;
    const int ctid = lane & 3;

    // prologue: row inverse sums
    if (tid < 128) {
        const float* pp = g_partials + ((size_t)bh * SS + m0 + tid) * 32;
        float s = 0.f;
        #pragma unroll
        for (int i = 0; i < 32; i++) s += pp[i];
        invs[tid] = 1.f / s;
    }
    __syncthreads();

    float acc[2][4][4];
    #pragma unroll
    for (int i = 0; i < 2; i++)
        #pragma unroll
        for (int j = 0; j < 4; j++)
            #pragma unroll
            for (int q = 0; q < 4; q++) acc[i][j][q] = 0.f;

    for (int kg = 0; kg < SS; kg += 32) {
        const int kg2 = kg >> 1;
        __syncthreads();
        // stage A: pure copy of exp planes; reconstruct+scale -> probs write
        #pragma unroll
        for (int p = 0; p < 2; p++) {
            int idx = tid + p * 256;
            int r   = idx >> 2;
            int w4  = (idx & 3) << 2;
            size_t src = ((size_t)(m0 + r)) * 512 + kg2 + w4;
            uint4 hv = *(const uint4*)(php + src);
            uint4 lv = *(const uint4*)(plp + src);
            *(uint4*)(AH + r * CX_AP + w4) = hv;
            *(uint4*)(AL + r * CX_AP + w4) = lv;

            // normalized fp32 probs writeback (8 elements)
            float iv = invs[r];
            float2 h0 = __bfloat1622float2(*(__nv_bfloat162*)&hv.x);
            float2 l0 = __bfloat1622float2(*(__nv_bfloat162*)&lv.x);
            float2 h1 = __bfloat1622float2(*(__nv_bfloat162*)&hv.y);
            float2 l1 = __bfloat1622float2(*(__nv_bfloat162*)&lv.y);
            float2 h2 = __bfloat1622float2(*(__nv_bfloat162*)&hv.z);
            float2 l2 = __bfloat1622float2(*(__nv_bfloat162*)&lv.z);
            float2 h3 = __bfloat1622float2(*(__nv_bfloat162*)&hv.w);
            float2 l3 = __bfloat1622float2(*(__nv_bfloat162*)&lv.w);
            float4 o0 = make_float4((h0.x + l0.x) * iv, (h0.y + l0.y) * iv,
                                    (h1.x + l1.x) * iv, (h1.y + l1.y) * iv);
            float4 o1 = make_float4((h2.x + l2.x) * iv, (h2.y + l2.y) * iv,
                                    (h3.x + l3.x) * iv, (h3.y + l3.y) * iv);
            float* pw = pout + (size_t)(m0 + r) * SS + kg + (idx & 3) * 8;
            *(float4*)pw       = o0;
            *(float4*)(pw + 4) = o1;
        }
        // stage B (V): split in staging (unchanged R13)
        {
            int j  = tid >> 4;
            int d4 = (tid & 15) << 2;
            const float* vr = vb + (size_t)(kg + 2 * j) * EE + d4;
            float4 r0 = *(const float4*)vr;
            float4 r1 = *(const float4*)(vr + EE);
            uint4 hv, lv;
            split2_bf16(r0.x, r1.x, hv.x, lv.x);
            split2_bf16(r0.y, r1.y, hv.y, lv.y);
            split2_bf16(r0.z, r1.z, hv.z, lv.z);
            split2_bf16(r0.w, r1.w, hv.w, lv.w);
            *(uint4*)(BH + j * CX_BP + d4) = hv;
            *(uint4*)(BL + j * CX_BP + d4) = lv;
        }
        __syncthreads();

        #pragma unroll
        for (int kwb = 0; kwb < 16; kwb += 8) {
            uint32_t ah[2][4], al[2][4];
            #pragma unroll
            for (int mt = 0; mt < 2; mt++) {
                int mrow = wm * 32 + mt * 16 + gid;
                const uint32_t* ph = AH + mrow * CX_AP + kwb + ctid;
                const uint32_t* pl = AL + mrow * CX_AP + kwb + ctid;
                ah[mt][0] = ph[0];          ah[mt][1] = ph[8*CX_AP];
                ah[mt][2] = ph[4];          ah[mt][3] = ph[8*CX_AP + 4];
                al[mt][0] = pl[0];          al[mt][1] = pl[8*CX_AP];
                al[mt][2] = pl[4];          al[mt][3] = pl[8*CX_AP + 4];
            }
            uint32_t bhv[4][2], blv[4][2];
            #pragma unroll
            for (int nt = 0; nt < 4; nt++) {
                int nrow = wn * 32 + nt * 8 + gid;
                const uint32_t* pbh = BH + (kwb + ctid) * CX_BP + nrow;
                const uint32_t* pbl = BL + (kwb + ctid) * CX_BP + nrow;
                bhv[nt][0] = pbh[0]; bhv[nt][1] = pbh[4*CX_BP];
                blv[nt][0] = pbl[0]; blv[nt][1] = pbl[4*CX_BP];
            }
            MMA_PASSES(acc, ah, al, bhv, blv);
        }
    }

    // epilogue: scale by inv[row]
    #pragma unroll
    for (int mt = 0; mt < 2; mt++) {
        int lrow = wm * 32 + mt * 16 + gid;
        float ci0 = invs[lrow];
        float ci1 = invs[lrow + 8];
        #pragma unroll
        for (int nt = 0; nt < 4; nt++) {
            int col = wn * 32 + nt * 8 + 2 * ctid;
            float* op = g_ctx + ((size_t)b * SS + m0 + lrow) * EE + h * DD + col;
            *(float2*)op = make_float2(acc[mt][nt][0] * ci0, acc[mt][nt][1] * ci0);
            *(float2*)(op + (size_t)8 * EE) =
                make_float2(acc[mt][nt][2] * ci1, acc[mt][nt][3] * ci1);
        }
    }
}

// =============================================================================
// Kernel 3: output projection (R13, unchanged).
// =============================================================================
#define GF_AP 20
#define GF_AHo 0
#define GF_ALo 2560
#define GF_BHo 5120
#define GF_BLo 6400
#define GF_SMEM_WORDS 7680
#define GF_SMEM_BYTES (GF_SMEM_WORDS * 4)

__global__ __launch_bounds__(256) void fc_mma_kernel(
    const float* __restrict__ fcw, const float* __restrict__ fcb,
    float* __restrict__ out)
{
    extern __shared__ uint32_t su[];
    uint32_t* AH = su + GF_AHo;
    uint32_t* AL = su + GF_ALo;
    uint32_t* BH = su + GF_BHo;
    uint32_t* BL = su + GF_BLo;

    const int b  = blockIdx.z;
    const int m0 = blockIdx.x * 128;
    const int n0 = blockIdx.y * 64;

    const float* ctx = g_ctx + (size_t)b * SS * EE;

    const int tid  = threadIdx.x;
    const int lane = tid & 31;
    const int w8   = tid >> 5;
    const int wm   = w8 >> 1;
    const int wn   = w8 & 1;
    const int gid  = lane >> 2;
    const int ctid = lane & 3;

    float acc[2][4][4];
    #pragma unroll
    for (int i = 0; i < 2; i++)
        #pragma unroll
        for (int j = 0; j < 4; j++)
            #pragma unroll
            for (int q = 0; q < 4; q++) acc[i][j][q] = 0.f;

    for (int kg = 0; kg < EE; kg += 32) {
        __syncthreads();
        #pragma unroll
        for (int p = 0; p < 2; p++) {
            int idx = tid + p * 256;
            int r   = idx >> 2;
            int kq  = (idx & 3) << 3;
            const float* ar = fcw + (size_t)(m0 + r) * EE + kg + kq;
            float4 a0 = *(const float4*)ar;
            float4 a1 = *(const float4*)(ar + 4);
            uint4 hv, lv;
            split2_bf16(a0.x, a0.y, hv.x, lv.x);
            split2_bf16(a0.z, a0.w, hv.y, lv.y);
            split2_bf16(a1.x, a1.y, hv.z, lv.z);
            split2_bf16(a1.z, a1.w, hv.w, lv.w);
            *(uint4*)(AH + r * GF_AP + (idx & 3) * 4) = hv;
            *(uint4*)(AL + r * GF_AP + (idx & 3) * 4) = lv;
        }
        {
            int r  = tid >> 2;
            int kq = (tid & 3) << 3;
            const float* br = ctx + (size_t)(n0 + r) * EE + kg + kq;
            float4 b0 = *(const float4*)br;
            float4 b1 = *(const float4*)(br + 4);
            uint4 hv, lv;
            split2_bf16(b0.x, b0.y, hv.x, lv.x);
            split2_bf16(b0.z, b0.w, hv.y, lv.y);
            split2_bf16(b1.x, b1.y, hv.z, lv.z);
            split2_bf16(b1.z, b1.w, hv.w, lv.w);
            *(uint4*)(BH + r * GF_AP + (tid & 3) * 4) = hv;
            *(uint4*)(BL + r * GF_AP + (tid & 3) * 4) = lv;
        }
        __syncthreads();

        #pragma unroll
        for (int kwb = 0; kwb < 16; kwb += 8) {
            uint32_t ah[2][4], al[2][4];
            #pragma unroll
            for (int mt = 0; mt < 2; mt++) {
                int mrow = wm * 32 + mt * 16 + gid;
                const uint32_t* ph = AH + mrow * GF_AP + kwb + ctid;
                const uint32_t* pl = AL + mrow * GF_AP + kwb + ctid;
                ah[mt][0] = ph[0];          ah[mt][1] = ph[8*GF_AP];
                ah[mt][2] = ph[4];          ah[mt][3] = ph[8*GF_AP + 4];
                al[mt][0] = pl[0];          al[mt][1] = pl[8*GF_AP];
                al[mt][2] = pl[4];          al[mt][3] = pl[8*GF_AP + 4];
            }
            uint32_t bhv[4][2], blv[4][2];
            #pragma unroll
            for (int nt = 0; nt < 4; nt++) {
                int nrow = wn * 32 + nt * 8 + gid;
                const uint32_t* pbh = BH + nrow * GF_AP + kwb + ctid;
                const uint32_t* pbl = BL + nrow * GF_AP + kwb + ctid;
                bhv[nt][0] = pbh[0]; bhv[nt][1] = pbh[4];
                blv[nt][0] = pbl[0]; blv[nt][1] = pbl[4];
            }
            MMA_PASSES(acc, ah, al, bhv, blv);
        }
    }

    #pragma unroll
    for (int mt = 0; mt < 2; mt++) {
        int row = m0 + wm * 32 + mt * 16 + gid;
        float fb0 = fcb[row];
        float fb1 = fcb[row + 8];
        #pragma unroll
        for (int nt = 0; nt < 4; nt++) {
            int col = n0 + wn * 32 + nt * 8 + 2 * ctid;
            *(float2*)(out + ((size_t)b * EE + row) * SS + col) =
                make_float2(acc[mt][nt][0] + fb0, acc[mt][nt][1] + fb0);
            *(float2*)(out + ((size_t)b * EE + row + 8) * SS + col) =
                make_float2(acc[mt][nt][2] + fb1, acc[mt][nt][3] + fb1);
        }
    }
}

// =============================================================================
extern "C" void kernel_launch(void* const* d_in, const int* in_sizes, int n_in,
                              void* d_out, int out_size)
{
    const float* q_img = (const float*)d_in[0];
    const float* k_img = (const float*)d_in[1];
    const float* v_img = (const float*)d_in[2];
    const float* wq_w  = (const float*)d_in[3];
    const float* wq_b  = (const float*)d_in[4];
    const float* wk_w  = (const float*)d_in[5];
    const float* wk_b  = (const float*)d_in[6];
    const float* wv_w  = (const float*)d_in[7];
    const float* wv_b  = (const float*)d_in[8];
    const float* fc_w  = (const float*)d_in[9];
    const float* fc_b  = (const float*)d_in[10];

    float* out   = (float*)d_out;
    float* probs = out + (size_t)BB * EE * SS;   // tuple output: (out, probs)

    cudaFuncSetAttribute(proj_mma_kernel, cudaFuncAttributeMaxDynamicSharedMemorySize,
                         GP_SMEM_BYTES);
    cudaFuncSetAttribute(scores_mma_kernel, cudaFuncAttributeMaxDynamicSharedMemorySize,
                         SK_SMEM_BYTES);
    cudaFuncSetAttribute(ctx_mma_kernel, cudaFuncAttributeMaxDynamicSharedMemorySize,
                         CX_SMEM_BYTES);
    cudaFuncSetAttribute(fc_mma_kernel, cudaFuncAttributeMaxDynamicSharedMemorySize,
                         GF_SMEM_BYTES);

    // 1) QKV projections
    proj_mma_kernel<<<dim3(SS / 128, EE / 64, 3 * BB), 256, GP_SMEM_BYTES>>>(
        q_img, k_img, v_img, wq_w, wk_w, wv_w, wq_b, wk_b, wv_b);

    // 2a) scores + exp -> bf16 planes + row partial sums
    scores_mma_kernel<<<dim3(SS / 128, SS / 64, BB * NH), 256, SK_SMEM_BYTES>>>();

    // 2c) ctx = P @ V (copy-staged planes; writes normalized probs + scaled ctx)
    ctx_mma_kernel<<<dim3(SS / 128, 1, BB * NH), 256, CX_SMEM_BYTES>>>(probs);

    // 3) output projection
    fc_mma_kernel<<<dim3(EE / 128, SS / 64, BB), 256, GF_SMEM_BYTES>>>(fc_w, fc_b, out);
}